// round 1
// baseline (speedup 1.0000x reference)
#include <cuda_runtime.h>
#include <math.h>

#define BB 8
#define SS 512
#define HH 256
#define AA 64
#define ROWS (BB*SS)   // 4096

// Scratch (allocation-free rule: __device__ globals)
__device__ float g_ta[ROWS * AA];    // [row][a], bias folded in
__device__ float g_jaT[AA * ROWS];   // [a][row]  (transposed for coalesced j reads)

__device__ __forceinline__ float tanh_fast(float x) {
    float y;
    asm("tanh.approx.f32 %0, %1;" : "=f"(y) : "f"(x));
    return y;
}

// ---------------------------------------------------------------------------
// Kernel 1: both projections. One block per row (b*S+i), 128 threads:
// threads 0..63 compute ta[row][a] (+bias), threads 64..127 compute ja -> jaT.
// ---------------------------------------------------------------------------
__global__ void __launch_bounds__(128) proj_kernel(
    const float* __restrict__ x,
    const float* __restrict__ w_ta,
    const float* __restrict__ w_ja,
    const float* __restrict__ bias)
{
    __shared__ float4 xs[HH / 4];

    const int row = blockIdx.x;
    const int tid = threadIdx.x;

    // cooperative load of x row (256 floats = 64 float4)
    const float4* xrow = reinterpret_cast<const float4*>(x + (size_t)row * HH);
    if (tid < HH / 4) xs[tid] = xrow[tid];
    __syncthreads();

    const int a = tid & 63;
    const float* w = (tid < 64) ? w_ta : w_ja;
    const float4* wrow = reinterpret_cast<const float4*>(w + (size_t)a * HH);

    float acc = 0.f;
#pragma unroll
    for (int h4 = 0; h4 < HH / 4; ++h4) {
        float4 wv = wrow[h4];
        float4 xv = xs[h4];
        acc = fmaf(wv.x, xv.x, acc);
        acc = fmaf(wv.y, xv.y, acc);
        acc = fmaf(wv.z, xv.z, acc);
        acc = fmaf(wv.w, xv.w, acc);
    }

    if (tid < 64) g_ta[row * AA + a] = acc + bias[a];
    else          g_jaT[a * ROWS + row] = acc;
}

// ---------------------------------------------------------------------------
// Kernel 2: scores + softmax. One block per (b,i), 512 threads = one j each.
// s[j] = sum_a v[a] * tanh(ta[i][a] + ja[j][a]); softmax over j.
// ---------------------------------------------------------------------------
__global__ void __launch_bounds__(512) attn_kernel(
    const float* __restrict__ v,
    float* __restrict__ out)
{
    __shared__ float ta_s[AA];
    __shared__ float vv[AA];
    __shared__ float red[16];
    __shared__ float bcast;

    const int row = blockIdx.x;          // b*S + i
    const int b   = row >> 9;
    const int j   = threadIdx.x;         // 0..511
    const int base = b << 9;             // row offset of this batch in jaT

    if (j < AA) {
        ta_s[j] = g_ta[row * AA + j];
        vv[j]   = v[j];
    }
    __syncthreads();

    float s = 0.f;
#pragma unroll
    for (int a = 0; a < AA; ++a) {
        float jv = g_jaT[a * ROWS + base + j];
        float t  = tanh_fast(ta_s[a] + jv);
        s = fmaf(vv[a], t, s);
    }

    const int lane = j & 31;
    const int warp = j >> 5;

    // ---- block max ----
    float mx = s;
#pragma unroll
    for (int o = 16; o; o >>= 1) mx = fmaxf(mx, __shfl_xor_sync(0xffffffffu, mx, o));
    if (lane == 0) red[warp] = mx;
    __syncthreads();
    if (warp == 0) {
        float m = (lane < 16) ? red[lane] : -INFINITY;
#pragma unroll
        for (int o = 8; o; o >>= 1) m = fmaxf(m, __shfl_xor_sync(0xffffffffu, m, o));
        if (lane == 0) bcast = m;
    }
    __syncthreads();
    const float gmax = bcast;

    // ---- exp + block sum ----
    float e = __expf(s - gmax);
    float sm = e;
#pragma unroll
    for (int o = 16; o; o >>= 1) sm += __shfl_xor_sync(0xffffffffu, sm, o);
    if (lane == 0) red[warp] = sm;
    __syncthreads();
    if (warp == 0) {
        float t = (lane < 16) ? red[lane] : 0.f;
#pragma unroll
        for (int o = 8; o; o >>= 1) t += __shfl_xor_sync(0xffffffffu, t, o);
        if (lane == 0) bcast = t;
    }
    __syncthreads();
    const float inv = __frcp_rn(bcast);

    out[(size_t)row * SS + j] = e * inv;
}

// ---------------------------------------------------------------------------
extern "C" void kernel_launch(void* const* d_in, const int* in_sizes, int n_in,
                              void* d_out, int out_size)
{
    const float* x    = (const float*)d_in[0];  // relation_hidden (B,S,H)
    const float* wta  = (const float*)d_in[1];  // (A,H)
    const float* wja  = (const float*)d_in[2];  // (A,H)
    const float* bias = (const float*)d_in[3];  // (1,1,1,A)
    const float* v    = (const float*)d_in[4];  // (1,A)

    proj_kernel<<<ROWS, 128>>>(x, wta, wja, bias);
    attn_kernel<<<ROWS, 512>>>(v, (float*)d_out);
}

// round 2
// speedup vs baseline: 2.9495x; 2.9495x over previous
#include <cuda_runtime.h>
#include <math.h>

#define BB 8
#define SS 512
#define HH 256
#define AA 64
#define ROWS (BB*SS)   // 4096
#define TI 8           // i-rows per attn block

// Scratch (allocation-free rule: __device__ globals)
__device__ float g_ta[ROWS * AA];      // [row][a], bias folded in
__device__ float g_jaT[AA * ROWS];     // [a][row]  (coalesced j reads)
__device__ float g_wT[HH * 128];       // [k][a2]: a2<64 -> w_ta, a2>=64 -> w_ja

__device__ __forceinline__ float tanh_fast(float x) {
    float y;
    asm("tanh.approx.f32 %0, %1;" : "=f"(y) : "f"(x));
    return y;
}

// ---------------------------------------------------------------------------
// Kernel 0: transpose + concat weights into g_wT[k][a2] (k-major, coalesced
// for the GEMM's smem loads). 256 blocks (k), 128 threads (a2). Tiny.
// ---------------------------------------------------------------------------
__global__ void __launch_bounds__(128) wtrans_kernel(
    const float* __restrict__ w_ta,
    const float* __restrict__ w_ja)
{
    const int k  = blockIdx.x;     // 0..255
    const int a2 = threadIdx.x;    // 0..127
    float val = (a2 < 64) ? w_ta[a2 * HH + k] : w_ja[(a2 - 64) * HH + k];
    g_wT[k * 128 + a2] = val;
}

// ---------------------------------------------------------------------------
// Kernel 1: tiled GEMM. 128 blocks x 256 threads. Each block: 32 rows x 128
// cols (64 ta + 64 ja). Thread (rt,ct) owns a 4x4 micro-tile.
// ---------------------------------------------------------------------------
#define KC 64
__global__ void __launch_bounds__(256) proj_gemm_kernel(
    const float* __restrict__ x,
    const float* __restrict__ bias)
{
    __shared__ float Xs[32][KC];        // [r][kk]  8KB
    __shared__ float Ws[KC][128];       // [kk][a2] 32KB

    const int tid = threadIdx.x;
    const int rt  = tid >> 5;           // 0..7  (row tile)
    const int ct  = tid & 31;           // 0..31 (col tile)
    const int row0 = blockIdx.x * 32;

    float acc[4][4];
#pragma unroll
    for (int i = 0; i < 4; ++i)
#pragma unroll
        for (int jj = 0; jj < 4; ++jj) acc[i][jj] = 0.f;

    for (int kc = 0; kc < HH; kc += KC) {
        // Load X chunk: 32 rows x 64 k = 512 float4, 2 per thread (coalesced).
#pragma unroll
        for (int l = tid; l < 512; l += 256) {
            int r = l >> 4;            // 0..31
            int q = l & 15;            // float4 within row
            float4 xv = *reinterpret_cast<const float4*>(
                x + (size_t)(row0 + r) * HH + kc + q * 4);
            *reinterpret_cast<float4*>(&Xs[r][q * 4]) = xv;
        }
        // Load W chunk: 64 k-rows x 128 cols = 2048 float4 / 4 = ... 8 per thread.
#pragma unroll
        for (int l = tid; l < 2048; l += 256) {
            int kk = l >> 5;           // 0..63
            int q  = l & 31;           // float4 within 128-col row
            *reinterpret_cast<float4*>(&Ws[kk][q * 4]) =
                *reinterpret_cast<const float4*>(g_wT + (size_t)(kc + kk) * 128 + q * 4);
        }
        __syncthreads();

#pragma unroll
        for (int kk = 0; kk < KC; ++kk) {
            float4 w4 = *reinterpret_cast<float4*>(&Ws[kk][ct * 4]); // conflict-free
            float x0 = Xs[rt * 4 + 0][kk];   // broadcasts within warp
            float x1 = Xs[rt * 4 + 1][kk];
            float x2 = Xs[rt * 4 + 2][kk];
            float x3 = Xs[rt * 4 + 3][kk];
            acc[0][0] = fmaf(x0, w4.x, acc[0][0]);
            acc[0][1] = fmaf(x0, w4.y, acc[0][1]);
            acc[0][2] = fmaf(x0, w4.z, acc[0][2]);
            acc[0][3] = fmaf(x0, w4.w, acc[0][3]);
            acc[1][0] = fmaf(x1, w4.x, acc[1][0]);
            acc[1][1] = fmaf(x1, w4.y, acc[1][1]);
            acc[1][2] = fmaf(x1, w4.z, acc[1][2]);
            acc[1][3] = fmaf(x1, w4.w, acc[1][3]);
            acc[2][0] = fmaf(x2, w4.x, acc[2][0]);
            acc[2][1] = fmaf(x2, w4.y, acc[2][1]);
            acc[2][2] = fmaf(x2, w4.z, acc[2][2]);
            acc[2][3] = fmaf(x2, w4.w, acc[2][3]);
            acc[3][0] = fmaf(x3, w4.x, acc[3][0]);
            acc[3][1] = fmaf(x3, w4.y, acc[3][1]);
            acc[3][2] = fmaf(x3, w4.z, acc[3][2]);
            acc[3][3] = fmaf(x3, w4.w, acc[3][3]);
        }
        __syncthreads();
    }

    const int c0 = ct * 4;
    if (c0 < 64) {
        // ta path: add bias, write [row][a] as float4
        float4 bb = *reinterpret_cast<const float4*>(bias + c0);
#pragma unroll
        for (int i = 0; i < 4; ++i) {
            int row = row0 + rt * 4 + i;
            float4 o;
            o.x = acc[i][0] + bb.x;
            o.y = acc[i][1] + bb.y;
            o.z = acc[i][2] + bb.z;
            o.w = acc[i][3] + bb.w;
            *reinterpret_cast<float4*>(&g_ta[(size_t)row * AA + c0]) = o;
        }
    } else {
        // ja path: write transposed [a][row]
#pragma unroll
        for (int jj = 0; jj < 4; ++jj) {
            int a = c0 - 64 + jj;
#pragma unroll
            for (int i = 0; i < 4; ++i) {
                int row = row0 + rt * 4 + i;
                g_jaT[(size_t)a * ROWS + row] = acc[i][jj];
            }
        }
    }
}

// ---------------------------------------------------------------------------
// Kernel 2: scores + softmax, TI=8 i-rows per block (8x less jaT traffic).
// 512 blocks x 512 threads; thread = one j.
// ---------------------------------------------------------------------------
__global__ void __launch_bounds__(512) attn_kernel(
    const float* __restrict__ v,
    float* __restrict__ out)
{
    __shared__ float ta_s[TI][AA];
    __shared__ float vv[AA];
    __shared__ float redm[TI][16];
    __shared__ float reds[TI][16];
    __shared__ float gmaxs[TI];
    __shared__ float sums[TI];

    const int blk = blockIdx.x;           // 0..511
    const int b   = blk >> 6;             // batch
    const int i0  = (blk & 63) * TI;      // first i-row
    const int j   = threadIdx.x;          // 0..511
    const int lane = j & 31;
    const int warp = j >> 5;              // 0..15

    // load TI rows of ta (512 floats) + v
    {
        int r = j >> 6, a = j & 63;
        ta_s[r][a] = g_ta[(size_t)(b * SS + i0 + r) * AA + a];
        if (j < AA) vv[j] = v[j];
    }
    __syncthreads();

    float s[TI];
#pragma unroll
    for (int i = 0; i < TI; ++i) s[i] = 0.f;

    const float* jp = g_jaT + b * SS + j;
#pragma unroll
    for (int a = 0; a < AA; ++a) {
        float jv = jp[(size_t)a * ROWS];
        float va = vv[a];
#pragma unroll
        for (int i = 0; i < TI; ++i) {
            s[i] = fmaf(va, tanh_fast(ta_s[i][a] + jv), s[i]);
        }
    }

    // ---- block max per row ----
#pragma unroll
    for (int i = 0; i < TI; ++i) {
        float mx = s[i];
#pragma unroll
        for (int o = 16; o; o >>= 1) mx = fmaxf(mx, __shfl_xor_sync(0xffffffffu, mx, o));
        if (lane == 0) redm[i][warp] = mx;
    }
    __syncthreads();
    if (warp < TI) {
        float m = (lane < 16) ? redm[warp][lane] : -INFINITY;
#pragma unroll
        for (int o = 8; o; o >>= 1) m = fmaxf(m, __shfl_xor_sync(0xffffffffu, m, o));
        if (lane == 0) gmaxs[warp] = m;
    }
    __syncthreads();

    // ---- exp + block sum per row ----
    float e[TI];
#pragma unroll
    for (int i = 0; i < TI; ++i) {
        e[i] = __expf(s[i] - gmaxs[i]);
        float sm = e[i];
#pragma unroll
        for (int o = 16; o; o >>= 1) sm += __shfl_xor_sync(0xffffffffu, sm, o);
        if (lane == 0) reds[i][warp] = sm;
    }
    __syncthreads();
    if (warp < TI) {
        float t = (lane < 16) ? reds[warp][lane] : 0.f;
#pragma unroll
        for (int o = 8; o; o >>= 1) t += __shfl_xor_sync(0xffffffffu, t, o);
        if (lane == 0) sums[warp] = t;
    }
    __syncthreads();

#pragma unroll
    for (int i = 0; i < TI; ++i) {
        float inv = __frcp_rn(sums[i]);
        out[(size_t)(b * SS + i0 + i) * SS + j] = e[i] * inv;
    }
}

// ---------------------------------------------------------------------------
extern "C" void kernel_launch(void* const* d_in, const int* in_sizes, int n_in,
                              void* d_out, int out_size)
{
    const float* x    = (const float*)d_in[0];  // relation_hidden (B,S,H)
    const float* wta  = (const float*)d_in[1];  // (A,H)
    const float* wja  = (const float*)d_in[2];  // (A,H)
    const float* bias = (const float*)d_in[3];  // (1,1,1,A)
    const float* v    = (const float*)d_in[4];  // (1,A)

    wtrans_kernel<<<HH, 128>>>(wta, wja);
    proj_gemm_kernel<<<ROWS / 32, 256>>>(x, bias);
    attn_kernel<<<ROWS / TI, 512>>>(v, (float*)d_out);
}

// round 3
// speedup vs baseline: 2.9512x; 1.0006x over previous
#include <cuda_runtime.h>
#include <math.h>

#define BB 8
#define SS 512
#define HH 256
#define AA 64
#define ROWS (BB*SS)   // 4096
#define TI 8           // i-rows per attn block

// Scratch (allocation-free rule: __device__ globals)
__device__ float g_ta[ROWS * AA];      // [row][a], bias folded in
__device__ float g_jaT[AA * ROWS];     // [a][row]  (coalesced j reads)
__device__ float g_wT[HH * 128];       // [k][a2]: a2<64 -> w_ta, a2>=64 -> w_ja

__device__ __forceinline__ float tanh_fast(float x) {
    float y;
    asm("tanh.approx.f32 %0, %1;" : "=f"(y) : "f"(x));
    return y;
}

// packed f32x2 helpers (Blackwell FFMA2 — only reachable via PTX fma.rn.f32x2)
union F2 { unsigned long long u; float2 f; };

__device__ __forceinline__ unsigned long long fma2(
    unsigned long long a, unsigned long long b, unsigned long long c) {
    unsigned long long d;
    asm("fma.rn.f32x2 %0, %1, %2, %3;" : "=l"(d) : "l"(a), "l"(b), "l"(c));
    return d;
}

// ---------------------------------------------------------------------------
// Kernel 0: transpose + concat weights into g_wT[k][a2].
// 32 blocks x 256 threads; coalesced float4 reads, scattered scalar writes.
// ---------------------------------------------------------------------------
__global__ void __launch_bounds__(256) wtrans_kernel(
    const float* __restrict__ w_ta,
    const float* __restrict__ w_ja)
{
    const int t  = threadIdx.x;
    const int r  = t >> 6;                    // 0..3
    const int q  = t & 63;                    // float4 index over 256 k
    const int a2 = blockIdx.x * 4 + r;        // 0..127

    const float* src = (a2 < 64) ? (w_ta + (size_t)a2 * HH)
                                 : (w_ja + (size_t)(a2 - 64) * HH);
    float4 wv = *reinterpret_cast<const float4*>(src + q * 4);

    const int k0 = q * 4;
    g_wT[(size_t)(k0 + 0) * 128 + a2] = wv.x;
    g_wT[(size_t)(k0 + 1) * 128 + a2] = wv.y;
    g_wT[(size_t)(k0 + 2) * 128 + a2] = wv.z;
    g_wT[(size_t)(k0 + 3) * 128 + a2] = wv.w;
}

// ---------------------------------------------------------------------------
// Kernel 1: tiled GEMM with packed f32x2 FMA. 128 blocks x 256 threads.
// Block: 32 rows x 128 cols. Thread (rt,ct): 4x4 micro-tile, cols paired.
// ---------------------------------------------------------------------------
#define KC 64
__global__ void __launch_bounds__(256) proj_gemm_kernel(
    const float* __restrict__ x,
    const float* __restrict__ bias)
{
    __shared__ float Xs[32][KC];        // [r][kk]  8KB
    __shared__ float Ws[KC][128];       // [kk][a2] 32KB

    const int tid = threadIdx.x;
    const int rt  = tid >> 5;           // 0..7  (row tile)
    const int ct  = tid & 31;           // 0..31 (col tile)
    const int row0 = blockIdx.x * 32;

    F2 acc[4][2];                        // 4 rows x (2 col-pairs)
#pragma unroll
    for (int i = 0; i < 4; ++i) { acc[i][0].u = 0ull; acc[i][1].u = 0ull; }

    for (int kc = 0; kc < HH; kc += KC) {
        // X chunk: 32 rows x 64 k = 512 float4, 2 per thread (coalesced).
#pragma unroll
        for (int l = tid; l < 512; l += 256) {
            int r = l >> 4;
            int q = l & 15;
            float4 xv = *reinterpret_cast<const float4*>(
                x + (size_t)(row0 + r) * HH + kc + q * 4);
            *reinterpret_cast<float4*>(&Xs[r][q * 4]) = xv;
        }
        // W chunk: 64 k-rows x 128 cols, 8 float4 per thread (coalesced).
#pragma unroll
        for (int l = tid; l < 2048; l += 256) {
            int kk = l >> 5;
            int q  = l & 31;
            *reinterpret_cast<float4*>(&Ws[kk][q * 4]) =
                *reinterpret_cast<const float4*>(g_wT + (size_t)(kc + kk) * 128 + q * 4);
        }
        __syncthreads();

#pragma unroll
        for (int kk = 0; kk < KC; ++kk) {
            // LDS.128 -> two 64-bit f32x2 operands, no packing needed
            ulonglong2 wv = *reinterpret_cast<ulonglong2*>(&Ws[kk][ct * 4]);
            F2 x0, x1, x2, x3;
            float a0 = Xs[rt * 4 + 0][kk];
            float a1 = Xs[rt * 4 + 1][kk];
            float a2v = Xs[rt * 4 + 2][kk];
            float a3 = Xs[rt * 4 + 3][kk];
            x0.f = make_float2(a0, a0);
            x1.f = make_float2(a1, a1);
            x2.f = make_float2(a2v, a2v);
            x3.f = make_float2(a3, a3);
            acc[0][0].u = fma2(x0.u, wv.x, acc[0][0].u);
            acc[0][1].u = fma2(x0.u, wv.y, acc[0][1].u);
            acc[1][0].u = fma2(x1.u, wv.x, acc[1][0].u);
            acc[1][1].u = fma2(x1.u, wv.y, acc[1][1].u);
            acc[2][0].u = fma2(x2.u, wv.x, acc[2][0].u);
            acc[2][1].u = fma2(x2.u, wv.y, acc[2][1].u);
            acc[3][0].u = fma2(x3.u, wv.x, acc[3][0].u);
            acc[3][1].u = fma2(x3.u, wv.y, acc[3][1].u);
        }
        __syncthreads();
    }

    const int c0 = ct * 4;
    if (c0 < 64) {
        // ta path: add bias, write [row][a] as float4
        float4 bb = *reinterpret_cast<const float4*>(bias + c0);
#pragma unroll
        for (int i = 0; i < 4; ++i) {
            int row = row0 + rt * 4 + i;
            float4 o;
            o.x = acc[i][0].f.x + bb.x;
            o.y = acc[i][0].f.y + bb.y;
            o.z = acc[i][1].f.x + bb.z;
            o.w = acc[i][1].f.y + bb.w;
            *reinterpret_cast<float4*>(&g_ta[(size_t)row * AA + c0]) = o;
        }
    } else {
        // ja path: write transposed [a][row]
#pragma unroll
        for (int i = 0; i < 4; ++i) {
            int row = row0 + rt * 4 + i;
            int ab = c0 - 64;
            g_jaT[(size_t)(ab + 0) * ROWS + row] = acc[i][0].f.x;
            g_jaT[(size_t)(ab + 1) * ROWS + row] = acc[i][0].f.y;
            g_jaT[(size_t)(ab + 2) * ROWS + row] = acc[i][1].f.x;
            g_jaT[(size_t)(ab + 3) * ROWS + row] = acc[i][1].f.y;
        }
    }
}

// ---------------------------------------------------------------------------
// Kernel 2: scores + softmax, TI=8 i-rows per block. ta in [a][i] layout so
// each a needs only 2 broadcast LDS.128 instead of 8 scalar LDS.
// 512 blocks x 512 threads; thread = one j.
// ---------------------------------------------------------------------------
__global__ void __launch_bounds__(512) attn_kernel(
    const float* __restrict__ v,
    float* __restrict__ out)
{
    __shared__ float ta_s[AA][TI];      // [a][i], rows of 32B -> 16B aligned
    __shared__ float vv[AA];
    __shared__ float redm[TI][16];
    __shared__ float reds[TI][16];
    __shared__ float gmaxs[TI];
    __shared__ float sums[TI];

    const int blk = blockIdx.x;           // 0..511
    const int b   = blk >> 6;             // batch
    const int i0  = (blk & 63) * TI;      // first i-row
    const int j   = threadIdx.x;          // 0..511
    const int lane = j & 31;
    const int warp = j >> 5;              // 0..15

    // load TI rows of ta (transposed into [a][i]) + v
    {
        int a = j >> 3, r = j & 7;
        ta_s[a][r] = g_ta[(size_t)(b * SS + i0 + r) * AA + a];
        if (j < AA) vv[j] = v[j];
    }
    __syncthreads();

    float s[TI];
#pragma unroll
    for (int i = 0; i < TI; ++i) s[i] = 0.f;

    const float* jp = g_jaT + b * SS + j;
#pragma unroll
    for (int a = 0; a < AA; ++a) {
        float jv = jp[(size_t)a * ROWS];
        float va = vv[a];
        float4 tA = *reinterpret_cast<const float4*>(&ta_s[a][0]);
        float4 tB = *reinterpret_cast<const float4*>(&ta_s[a][4]);
        s[0] = fmaf(va, tanh_fast(tA.x + jv), s[0]);
        s[1] = fmaf(va, tanh_fast(tA.y + jv), s[1]);
        s[2] = fmaf(va, tanh_fast(tA.z + jv), s[2]);
        s[3] = fmaf(va, tanh_fast(tA.w + jv), s[3]);
        s[4] = fmaf(va, tanh_fast(tB.x + jv), s[4]);
        s[5] = fmaf(va, tanh_fast(tB.y + jv), s[5]);
        s[6] = fmaf(va, tanh_fast(tB.z + jv), s[6]);
        s[7] = fmaf(va, tanh_fast(tB.w + jv), s[7]);
    }

    // ---- block max per row ----
#pragma unroll
    for (int i = 0; i < TI; ++i) {
        float mx = s[i];
#pragma unroll
        for (int o = 16; o; o >>= 1) mx = fmaxf(mx, __shfl_xor_sync(0xffffffffu, mx, o));
        if (lane == 0) redm[i][warp] = mx;
    }
    __syncthreads();
    if (warp < TI) {
        float m = (lane < 16) ? redm[warp][lane] : -INFINITY;
#pragma unroll
        for (int o = 8; o; o >>= 1) m = fmaxf(m, __shfl_xor_sync(0xffffffffu, m, o));
        if (lane == 0) gmaxs[warp] = m;
    }
    __syncthreads();

    // ---- exp + block sum per row ----
    float e[TI];
#pragma unroll
    for (int i = 0; i < TI; ++i) {
        e[i] = __expf(s[i] - gmaxs[i]);
        float sm = e[i];
#pragma unroll
        for (int o = 16; o; o >>= 1) sm += __shfl_xor_sync(0xffffffffu, sm, o);
        if (lane == 0) reds[i][warp] = sm;
    }
    __syncthreads();
    if (warp < TI) {
        float t = (lane < 16) ? reds[warp][lane] : 0.f;
#pragma unroll
        for (int o = 8; o; o >>= 1) t += __shfl_xor_sync(0xffffffffu, t, o);
        if (lane == 0) sums[warp] = t;
    }
    __syncthreads();

#pragma unroll
    for (int i = 0; i < TI; ++i) {
        float inv = __frcp_rn(sums[i]);
        out[(size_t)(b * SS + i0 + i) * SS + j] = e[i] * inv;
    }
}

// ---------------------------------------------------------------------------
extern "C" void kernel_launch(void* const* d_in, const int* in_sizes, int n_in,
                              void* d_out, int out_size)
{
    const float* x    = (const float*)d_in[0];  // relation_hidden (B,S,H)
    const float* wta  = (const float*)d_in[1];  // (A,H)
    const float* wja  = (const float*)d_in[2];  // (A,H)
    const float* bias = (const float*)d_in[3];  // (1,1,1,A)
    const float* v    = (const float*)d_in[4];  // (1,A)

    wtrans_kernel<<<32, 256>>>(wta, wja);
    proj_gemm_kernel<<<ROWS / 32, 256>>>(x, bias);
    attn_kernel<<<ROWS / TI, 512>>>(v, (float*)d_out);
}

// round 6
// speedup vs baseline: 3.0637x; 1.0381x over previous
#include <cuda_runtime.h>
#include <cuda_fp16.h>
#include <math.h>

#define BB 8
#define SS 512
#define HH 256
#define AA 64
#define ROWS (BB*SS)   // 4096
#define TI 8           // i-rows per attn block

// Scratch (allocation-free rule: __device__ globals)
__device__ float        g_ta[ROWS * AA];         // [row][a], bias folded in (f32)
__device__ unsigned int g_jaT16[(AA/2) * ROWS];  // [a-pair][row], half2 (ja_2p, ja_2p+1)
__device__ float        g_wT[HH * 128];          // [k][a2]: a2<64 -> w_ta, a2>=64 -> w_ja

namespace rk {

// packed f32x2 helpers (Blackwell FFMA2 — only reachable via PTX fma.rn.f32x2)
union F2 { unsigned long long u; float2 f; };

__device__ __forceinline__ unsigned long long fma2(
    unsigned long long a, unsigned long long b, unsigned long long c) {
    unsigned long long d;
    asm("fma.rn.f32x2 %0, %1, %2, %3;" : "=l"(d) : "l"(a), "l"(b), "l"(c));
    return d;
}

// fast packed tanh (MUFU.TANH f16x2) — unique name, no header collision
__device__ __forceinline__ __half2 rk_tanh_f16x2(__half2 x) {
    unsigned int xi = *reinterpret_cast<unsigned int*>(&x);
    unsigned int yi;
    asm("tanh.approx.f16x2 %0, %1;" : "=r"(yi) : "r"(xi));
    return *reinterpret_cast<__half2*>(&yi);
}

} // namespace rk

using rk::F2;
using rk::fma2;
using rk::rk_tanh_f16x2;

// ---------------------------------------------------------------------------
// Kernel 0: W transpose+concat via smem tile: coalesced reads AND writes.
// 8 blocks x 256 threads; each block does 32 k-values x 128 a2.
// ---------------------------------------------------------------------------
__global__ void __launch_bounds__(256) wtrans_kernel(
    const float* __restrict__ w_ta,
    const float* __restrict__ w_ja)
{
    __shared__ float tile[128][33];   // pad 33: phase-2 LDS conflict-free

    const int t  = threadIdx.x;
    const int k0 = blockIdx.x * 32;

    // Phase 1: read w[a2][k0+kk], lanes over kk (coalesced 128B per warp)
#pragma unroll
    for (int iter = 0; iter < 16; ++iter) {
        int kk = t & 31;
        int a2 = (t >> 5) + iter * 8;
        const float* src = (a2 < 64) ? (w_ta + (size_t)a2 * HH)
                                     : (w_ja + (size_t)(a2 - 64) * HH);
        tile[a2][kk] = src[k0 + kk];
    }
    __syncthreads();

    // Phase 2: write g_wT[k][a2], lanes over a2 (coalesced 512B per warp)
#pragma unroll
    for (int iter = 0; iter < 16; ++iter) {
        int idx = iter * 256 + t;
        int a2  = idx & 127;
        int kk  = idx >> 7;
        g_wT[(size_t)(k0 + kk) * 128 + a2] = tile[a2][kk];
    }
}

// ---------------------------------------------------------------------------
// Kernel 1: tiled GEMM with packed f32x2 FMA. 128 blocks x 256 threads.
// Block: 32 rows x 128 cols. Thread (rt,ct): 4x4 micro-tile, cols paired.
// Epilogue: ta -> f32 [row][a] (+bias); ja -> f16x2 [a-pair][row].
// ---------------------------------------------------------------------------
#define KC 64
__global__ void __launch_bounds__(256) proj_gemm_kernel(
    const float* __restrict__ x,
    const float* __restrict__ bias)
{
    __shared__ float Xs[32][KC];        // [r][kk]  8KB
    __shared__ float Ws[KC][128];       // [kk][a2] 32KB

    const int tid = threadIdx.x;
    const int rt  = tid >> 5;           // 0..7  (row tile)
    const int ct  = tid & 31;           // 0..31 (col tile)
    const int row0 = blockIdx.x * 32;

    F2 acc[4][2];                        // 4 rows x (2 col-pairs)
#pragma unroll
    for (int i = 0; i < 4; ++i) { acc[i][0].u = 0ull; acc[i][1].u = 0ull; }

    for (int kc = 0; kc < HH; kc += KC) {
#pragma unroll
        for (int l = tid; l < 512; l += 256) {
            int r = l >> 4;
            int q = l & 15;
            float4 xv = *reinterpret_cast<const float4*>(
                x + (size_t)(row0 + r) * HH + kc + q * 4);
            *reinterpret_cast<float4*>(&Xs[r][q * 4]) = xv;
        }
#pragma unroll
        for (int l = tid; l < 2048; l += 256) {
            int kk = l >> 5;
            int q  = l & 31;
            *reinterpret_cast<float4*>(&Ws[kk][q * 4]) =
                *reinterpret_cast<const float4*>(g_wT + (size_t)(kc + kk) * 128 + q * 4);
        }
        __syncthreads();

#pragma unroll
        for (int kk = 0; kk < KC; ++kk) {
            ulonglong2 wv = *reinterpret_cast<ulonglong2*>(&Ws[kk][ct * 4]);
            F2 x0, x1, x2, x3;
            float a0 = Xs[rt * 4 + 0][kk];
            float a1 = Xs[rt * 4 + 1][kk];
            float a2v = Xs[rt * 4 + 2][kk];
            float a3 = Xs[rt * 4 + 3][kk];
            x0.f = make_float2(a0, a0);
            x1.f = make_float2(a1, a1);
            x2.f = make_float2(a2v, a2v);
            x3.f = make_float2(a3, a3);
            acc[0][0].u = fma2(x0.u, wv.x, acc[0][0].u);
            acc[0][1].u = fma2(x0.u, wv.y, acc[0][1].u);
            acc[1][0].u = fma2(x1.u, wv.x, acc[1][0].u);
            acc[1][1].u = fma2(x1.u, wv.y, acc[1][1].u);
            acc[2][0].u = fma2(x2.u, wv.x, acc[2][0].u);
            acc[2][1].u = fma2(x2.u, wv.y, acc[2][1].u);
            acc[3][0].u = fma2(x3.u, wv.x, acc[3][0].u);
            acc[3][1].u = fma2(x3.u, wv.y, acc[3][1].u);
        }
        __syncthreads();
    }

    const int c0 = ct * 4;
    if (c0 < 64) {
        // ta path: add bias, write [row][a] as float4 (f32)
        float4 bb = *reinterpret_cast<const float4*>(bias + c0);
#pragma unroll
        for (int i = 0; i < 4; ++i) {
            int row = row0 + rt * 4 + i;
            float4 o;
            o.x = acc[i][0].f.x + bb.x;
            o.y = acc[i][0].f.y + bb.y;
            o.z = acc[i][1].f.x + bb.z;
            o.w = acc[i][1].f.y + bb.w;
            *reinterpret_cast<float4*>(&g_ta[(size_t)row * AA + c0]) = o;
        }
    } else {
        // ja path: f16x2 over a-pairs, [a-pair][row]; 4 consecutive rows -> STG.128
        const int ab  = c0 - 64;        // multiple of 4
        const int ap0 = ab >> 1;        // a-pair indices ap0, ap0+1
        uint4 s0, s1;
        {
            __half2 h;
            h = __floats2half2_rn(acc[0][0].f.x, acc[0][0].f.y); s0.x = *reinterpret_cast<unsigned int*>(&h);
            h = __floats2half2_rn(acc[1][0].f.x, acc[1][0].f.y); s0.y = *reinterpret_cast<unsigned int*>(&h);
            h = __floats2half2_rn(acc[2][0].f.x, acc[2][0].f.y); s0.z = *reinterpret_cast<unsigned int*>(&h);
            h = __floats2half2_rn(acc[3][0].f.x, acc[3][0].f.y); s0.w = *reinterpret_cast<unsigned int*>(&h);
            h = __floats2half2_rn(acc[0][1].f.x, acc[0][1].f.y); s1.x = *reinterpret_cast<unsigned int*>(&h);
            h = __floats2half2_rn(acc[1][1].f.x, acc[1][1].f.y); s1.y = *reinterpret_cast<unsigned int*>(&h);
            h = __floats2half2_rn(acc[2][1].f.x, acc[2][1].f.y); s1.z = *reinterpret_cast<unsigned int*>(&h);
            h = __floats2half2_rn(acc[3][1].f.x, acc[3][1].f.y); s1.w = *reinterpret_cast<unsigned int*>(&h);
        }
        const int rowb = row0 + rt * 4;   // multiple of 4 -> 16B aligned
        *reinterpret_cast<uint4*>(&g_jaT16[(size_t)ap0 * ROWS + rowb])       = s0;
        *reinterpret_cast<uint4*>(&g_jaT16[(size_t)(ap0 + 1) * ROWS + rowb]) = s1;
    }
}

// ---------------------------------------------------------------------------
// Kernel 2: scores + softmax with f16x2 tanh. TI=8 i-rows per block.
// 512 blocks x 512 threads; thread = one j. i-pairs ride the f16x2 lanes.
// ---------------------------------------------------------------------------
__global__ void __launch_bounds__(512) attn_kernel(
    const float* __restrict__ v,
    float* __restrict__ out)
{
    __shared__ __half2 ta16[AA][4];     // [a][i-pair p] = (ta[i0+2p], ta[i0+2p+1])
    __shared__ __half2 v16[AA];         // dup(v_a)
    __shared__ float redm[TI][16];
    __shared__ float reds[TI][16];
    __shared__ float gmaxs[TI];
    __shared__ float sums[TI];

    const int blk = blockIdx.x;           // 0..511
    const int b   = blk >> 6;             // batch
    const int i0  = (blk & 63) * TI;      // first i-row
    const int j   = threadIdx.x;          // 0..511
    const int lane = j & 31;
    const int warp = j >> 5;              // 0..15

    // setup: pack ta into f16x2 i-pairs, dup v
    if (j < 256) {
        int a = j >> 2, p = j & 3;
        float lo = g_ta[(size_t)(b * SS + i0 + 2 * p)     * AA + a];
        float hi = g_ta[(size_t)(b * SS + i0 + 2 * p + 1) * AA + a];
        ta16[a][p] = __floats2half2_rn(lo, hi);
    } else if (j < 256 + AA) {
        int a = j - 256;
        v16[a] = __float2half2_rn(v[a]);
    }
    __syncthreads();

    float acc[TI];
#pragma unroll
    for (int i = 0; i < TI; ++i) acc[i] = 0.f;

    const unsigned int* jp = g_jaT16 + b * SS + j;
#pragma unroll 4
    for (int ap = 0; ap < AA / 2; ++ap) {
        unsigned int jraw = jp[(size_t)ap * ROWS];
        __half2 jv  = *reinterpret_cast<__half2*>(&jraw);   // (ja_{2ap}, ja_{2ap+1})
        __half2 jv0 = __low2half2(jv);
        __half2 jv1 = __high2half2(jv);
        __half2 va0 = v16[2 * ap];
        __half2 va1 = v16[2 * ap + 1];
#pragma unroll
        for (int p = 0; p < 4; ++p) {
            __half2 t0 = rk_tanh_f16x2(__hadd2(ta16[2 * ap][p], jv0));
            __half2 t1 = rk_tanh_f16x2(__hadd2(ta16[2 * ap + 1][p], jv1));
            __half2 u  = __hfma2(va1, t1, __hmul2(va0, t0));
            float2 uf  = __half22float2(u);
            acc[2 * p]     += uf.x;
            acc[2 * p + 1] += uf.y;
        }
    }

    // ---- block max per row ----
#pragma unroll
    for (int i = 0; i < TI; ++i) {
        float mx = acc[i];
#pragma unroll
        for (int o = 16; o; o >>= 1) mx = fmaxf(mx, __shfl_xor_sync(0xffffffffu, mx, o));
        if (lane == 0) redm[i][warp] = mx;
    }
    __syncthreads();
    if (warp < TI) {
        float m = (lane < 16) ? redm[warp][lane] : -INFINITY;
#pragma unroll
        for (int o = 8; o; o >>= 1) m = fmaxf(m, __shfl_xor_sync(0xffffffffu, m, o));
        if (lane == 0) gmaxs[warp] = m;
    }
    __syncthreads();

    // ---- exp + block sum per row ----
    float e[TI];
#pragma unroll
    for (int i = 0; i < TI; ++i) {
        e[i] = __expf(acc[i] - gmaxs[i]);
        float sm = e[i];
#pragma unroll
        for (int o = 16; o; o >>= 1) sm += __shfl_xor_sync(0xffffffffu, sm, o);
        if (lane == 0) reds[i][warp] = sm;
    }
    __syncthreads();
    if (warp < TI) {
        float t = (lane < 16) ? reds[warp][lane] : 0.f;
#pragma unroll
        for (int o = 8; o; o >>= 1) t += __shfl_xor_sync(0xffffffffu, t, o);
        if (lane == 0) sums[warp] = t;
    }
    __syncthreads();

#pragma unroll
    for (int i = 0; i < TI; ++i) {
        float inv = __frcp_rn(sums[i]);
        out[(size_t)(b * SS + i0 + i) * SS + j] = e[i] * inv;
    }
}

// ---------------------------------------------------------------------------
extern "C" void kernel_launch(void* const* d_in, const int* in_sizes, int n_in,
                              void* d_out, int out_size)
{
    const float* x    = (const float*)d_in[0];  // relation_hidden (B,S,H)
    const float* wta  = (const float*)d_in[1];  // (A,H)
    const float* wja  = (const float*)d_in[2];  // (A,H)
    const float* bias = (const float*)d_in[3];  // (1,1,1,A)
    const float* v    = (const float*)d_in[4];  // (1,A)

    wtrans_kernel<<<8, 256>>>(wta, wja);
    proj_gemm_kernel<<<ROWS / 32, 256>>>(x, bias);
    attn_kernel<<<ROWS / TI, 512>>>(v, (float*)d_out);
}